// round 8
// baseline (speedup 1.0000x reference)
#include <cuda_runtime.h>
#include <cuda_bf16.h>

#define NP     19000
#define E_SG   1500000
#define N_SG   800000
#define ND     1024
#define B_DD   4096
#define NB     148
#define NT     512
#define NWARP  16
#define CHUNK  129
#define ASTR   264
#define NTILE  297

typedef unsigned long long ull;

// ---------------- persistent device state -----------------------------------
__device__ float    g_h1[NP * 256];
__device__ unsigned g_xb [NP * 128];
__device__ unsigned g_h1b[NP * 128];
__device__ unsigned g_h2b[NP * 128];
__device__ float    g_dinv[NP];
__device__ int      g_deg[NP];
__device__ int      g_rowstart[NP + 1];
__device__ int      g_fill[NP];
__device__ int      g_csr_src[E_SG];
__device__ float    g_drug[ND * 256];
__device__ int      g_drug_start[ND + 1];
__device__ int      g_part[NB];
__device__ int      g_poff[NB];
__device__ int      g_tctr[2];
__device__ unsigned g_cnt;
__device__ unsigned g_gen;

__device__ __forceinline__ unsigned pack2(float a, float b) {
    __nv_bfloat162 t = __floats2bfloat162_rn(a, b);
    return *(unsigned*)&t;
}
__device__ __forceinline__ float2 unpack2(unsigned u) {
    return __bfloat1622float2(*(__nv_bfloat162*)&u);
}
// packed f32x2 helpers (FFMA2 — ptxas never auto-emits; PTX-only)
__device__ __forceinline__ ull pk(float x, float y) {
    ull r; asm("mov.b64 %0, {%1, %2};" : "=l"(r) : "f"(x), "f"(y)); return r;
}
__device__ __forceinline__ float2 upk(ull v) {
    float2 f; asm("mov.b64 {%0, %1}, %2;" : "=f"(f.x), "=f"(f.y) : "l"(v)); return f;
}
__device__ __forceinline__ void ffma2(ull& d, ull a, ull b) {
    asm("fma.rn.f32x2 %0, %1, %2, %0;" : "+l"(d) : "l"(a), "l"(b));
}

// Software grid barrier; all 148 blocks co-resident (1 block/SM).
__device__ __forceinline__ void gridbar(unsigned gen0, unsigned k) {
    __syncthreads();
    if (threadIdx.x == 0) {
        __threadfence();
        unsigned pos = atomicAdd(&g_cnt, 1u);
        if (pos == NB - 1u) {
            atomicExch(&g_cnt, 0u);
            __threadfence();
            atomicAdd(&g_gen, 1u);
        } else {
            unsigned target = gen0 + k;
            while ((int)(*(volatile unsigned*)&g_gen - target) < 0) __nanosleep(64);
        }
        __threadfence();
    }
    __syncthreads();
}

// accumulate one bf16 row (uint4 = 8 bf16) * wd (packed w,w) into a2[4]
__device__ __forceinline__ void acc_row2(ull* a2, uint4 u, ull wd) {
    float2 f;
    f = unpack2(u.x); ffma2(a2[0], pk(f.x, f.y), wd);
    f = unpack2(u.y); ffma2(a2[1], pk(f.x, f.y), wd);
    f = unpack2(u.z); ffma2(a2[2], pk(f.x, f.y), wd);
    f = unpack2(u.w); ffma2(a2[3], pk(f.x, f.y), wd);
}

// ---------------- fused GCN layer: bf16 gather + f32x2 GEMM in smem ---------
__device__ void layer_phase(const uint4* __restrict__ inb, const float* __restrict__ W,
                            const float* __restrict__ bias, const float4* __restrict__ resid,
                            float4* __restrict__ out_f32, uint2* __restrict__ out_b16,
                            bool relu, int layer,
                            float* A, float* Bs, int* s_tile) {
    const int tid  = threadIdx.x;
    const int lane = tid & 31;
    const int wid  = tid >> 5;

    for (;;) {
        __syncthreads();
        if (tid == 0) *s_tile = atomicAdd(&g_tctr[layer], 1);
        __syncthreads();
        const int tile = *s_tile;
        if (tile >= NTILE) break;
        const int r0 = tile * 64;

        // ---- gather: warp wid produces rows wid*4 .. wid*4+3 (cols lane*8..+7)
        for (int i = 0; i < 4; i++) {
            int rr = wid * 4 + i;
            int r  = r0 + rr;
            ull a2[4] = {0ull, 0ull, 0ull, 0ull};
            float a[8];
            if (r < NP) {
                int beg = g_rowstart[r];
                int end = g_rowstart[r + 1];
                for (int base = beg; base < end; base += 32) {
                    int m = min(32, end - base);
                    int sidx = 0; float sw = 0.f;
                    if (lane < m) {
                        int s = g_csr_src[base + lane];
                        sidx = s * 32;
                        sw   = g_dinv[s];
                    }
                    int k = 0;
                    for (; k + 4 <= m; k += 4) {
                        int   i0 = __shfl_sync(0xffffffffu, sidx, k);
                        float w0 = __shfl_sync(0xffffffffu, sw,   k);
                        int   i1 = __shfl_sync(0xffffffffu, sidx, k + 1);
                        float w1 = __shfl_sync(0xffffffffu, sw,   k + 1);
                        int   i2 = __shfl_sync(0xffffffffu, sidx, k + 2);
                        float w2 = __shfl_sync(0xffffffffu, sw,   k + 2);
                        int   i3 = __shfl_sync(0xffffffffu, sidx, k + 3);
                        float w3 = __shfl_sync(0xffffffffu, sw,   k + 3);
                        uint4 u0 = inb[i0 + lane];
                        uint4 u1 = inb[i1 + lane];
                        uint4 u2 = inb[i2 + lane];
                        uint4 u3 = inb[i3 + lane];
                        acc_row2(a2, u0, pk(w0, w0));
                        acc_row2(a2, u1, pk(w1, w1));
                        acc_row2(a2, u2, pk(w2, w2));
                        acc_row2(a2, u3, pk(w3, w3));
                    }
                    for (; k < m; k++) {
                        int   i0 = __shfl_sync(0xffffffffu, sidx, k);
                        float w0 = __shfl_sync(0xffffffffu, sw,   k);
                        uint4 u0 = inb[i0 + lane];
                        acc_row2(a2, u0, pk(w0, w0));
                    }
                }
                float di = g_dinv[r];
                uint4 us = inb[r * 32 + lane];
                float2 f, g;
                f = upk(a2[0]); g = unpack2(us.x);
                a[0] = (f.x + g.x * di) * di; a[1] = (f.y + g.y * di) * di;
                f = upk(a2[1]); g = unpack2(us.y);
                a[2] = (f.x + g.x * di) * di; a[3] = (f.y + g.y * di) * di;
                f = upk(a2[2]); g = unpack2(us.z);
                a[4] = (f.x + g.x * di) * di; a[5] = (f.y + g.y * di) * di;
                f = upk(a2[3]); g = unpack2(us.w);
                a[6] = (f.x + g.x * di) * di; a[7] = (f.y + g.y * di) * di;
            } else {
                #pragma unroll
                for (int j = 0; j < 8; j++) a[j] = 0.f;
            }
            *(float4*)&A[rr * ASTR + lane * 8]     = make_float4(a[0], a[1], a[2], a[3]);
            *(float4*)&A[rr * ASTR + lane * 8 + 4] = make_float4(a[4], a[5], a[6], a[7]);
        }
        __syncthreads();

        // ---- GEMM: H[64,256] = A[64,256] * W[256,256], f32x2 packed FMA ----
        // output cols per thread: [lane*4, +4) and [128+lane*4, +4), as 4 col-pairs
        ull acc2[4][4];
        #pragma unroll
        for (int i = 0; i < 4; i++)
            #pragma unroll
            for (int j = 0; j < 4; j++) acc2[i][j] = 0ull;

        for (int k0 = 0; k0 < 256; k0 += 16) {
            #pragma unroll
            for (int q = 0; q < 2; q++) {
                int l  = tid + 512 * q;
                int br = l >> 6;
                int bc = (l & 63) * 4;
                *(float4*)&Bs[br * 256 + bc] = *(const float4*)&W[(k0 + br) * 256 + bc];
            }
            __syncthreads();
            #pragma unroll
            for (int k = 0; k < 16; k++) {
                float s0 = A[(wid * 4 + 0) * ASTR + k0 + k];
                float s1 = A[(wid * 4 + 1) * ASTR + k0 + k];
                float s2 = A[(wid * 4 + 2) * ASTR + k0 + k];
                float s3 = A[(wid * 4 + 3) * ASTR + k0 + k];
                float4 b0 = *(float4*)&Bs[k * 256 + lane * 4];
                float4 b1 = *(float4*)&Bs[k * 256 + 128 + lane * 4];
                ull ad0 = pk(s0, s0), ad1 = pk(s1, s1);
                ull ad2 = pk(s2, s2), ad3 = pk(s3, s3);
                ull bp0 = pk(b0.x, b0.y), bp1 = pk(b0.z, b0.w);
                ull bp2 = pk(b1.x, b1.y), bp3 = pk(b1.z, b1.w);
                ffma2(acc2[0][0], ad0, bp0); ffma2(acc2[0][1], ad0, bp1);
                ffma2(acc2[0][2], ad0, bp2); ffma2(acc2[0][3], ad0, bp3);
                ffma2(acc2[1][0], ad1, bp0); ffma2(acc2[1][1], ad1, bp1);
                ffma2(acc2[1][2], ad1, bp2); ffma2(acc2[1][3], ad1, bp3);
                ffma2(acc2[2][0], ad2, bp0); ffma2(acc2[2][1], ad2, bp1);
                ffma2(acc2[2][2], ad2, bp2); ffma2(acc2[2][3], ad2, bp3);
                ffma2(acc2[3][0], ad3, bp0); ffma2(acc2[3][1], ad3, bp1);
                ffma2(acc2[3][2], ad3, bp2); ffma2(acc2[3][3], ad3, bp3);
            }
            __syncthreads();
        }

        // ---- epilogue: bias (+residual) (+relu) -> fp32 and/or bf16 ----
        float4 bi0 = *(const float4*)&bias[lane * 4];
        float4 bi1 = *(const float4*)&bias[128 + lane * 4];
        #pragma unroll
        for (int i = 0; i < 4; i++) {
            int r = r0 + wid * 4 + i;
            if (r < NP) {
                float2 c0 = upk(acc2[i][0]), c1 = upk(acc2[i][1]);
                float2 c2 = upk(acc2[i][2]), c3 = upk(acc2[i][3]);
                float4 o0 = make_float4(c0.x + bi0.x, c0.y + bi0.y,
                                        c1.x + bi0.z, c1.y + bi0.w);
                float4 o1 = make_float4(c2.x + bi1.x, c2.y + bi1.y,
                                        c3.x + bi1.z, c3.y + bi1.w);
                if (resid) {
                    float4 r4 = resid[r * 64 + lane];
                    float4 r5 = resid[r * 64 + 32 + lane];
                    o0.x += r4.x; o0.y += r4.y; o0.z += r4.z; o0.w += r4.w;
                    o1.x += r5.x; o1.y += r5.y; o1.z += r5.z; o1.w += r5.w;
                }
                if (relu) {
                    o0.x = fmaxf(o0.x, 0.f); o0.y = fmaxf(o0.y, 0.f);
                    o0.z = fmaxf(o0.z, 0.f); o0.w = fmaxf(o0.w, 0.f);
                    o1.x = fmaxf(o1.x, 0.f); o1.y = fmaxf(o1.y, 0.f);
                    o1.z = fmaxf(o1.z, 0.f); o1.w = fmaxf(o1.w, 0.f);
                }
                if (out_f32) {
                    out_f32[r * 64 + lane]      = o0;
                    out_f32[r * 64 + 32 + lane] = o1;
                }
                if (out_b16) {
                    uint2 p0, p1;
                    p0.x = pack2(o0.x, o0.y); p0.y = pack2(o0.z, o0.w);
                    p1.x = pack2(o1.x, o1.y); p1.y = pack2(o1.z, o1.w);
                    out_b16[r * 64 + lane]      = p0;
                    out_b16[r * 64 + 32 + lane] = p1;
                }
            }
        }
    }
}

// ---------------- the single mega-kernel ------------------------------------
__global__ __launch_bounds__(NT, 1) void mega_kernel(
    const float* __restrict__ x, const int* __restrict__ ddb,
    const int* __restrict__ src, const int* __restrict__ dst,
    const int* __restrict__ nodes, const int* __restrict__ avgix,
    const float* __restrict__ W1, const float* __restrict__ b1,
    const float* __restrict__ W2, const float* __restrict__ b2,
    float* __restrict__ out)
{
    extern __shared__ float smem[];
    float* A  = smem;
    float* Bs = smem + 64 * ASTR;
    __shared__ unsigned s_gen0;
    __shared__ int s_tile;

    const int tid  = threadIdx.x;
    const int lane = tid & 31;
    const int wid  = tid >> 5;
    const int gtid = blockIdx.x * NT + tid;
    const int gs   = NB * NT;

    if (tid == 0) s_gen0 = *(volatile unsigned*)&g_gen;
    __syncthreads();
    const unsigned gen0 = s_gen0;

    // ---- P0: x -> bf16, degree histogram, drug boundaries, counter reset ----
    {
        const float2* x2 = (const float2*)x;
        for (int i = gtid; i < NP * 128; i += gs) {
            float2 v = x2[i];
            g_xb[i] = pack2(v.x, v.y);
        }
    }
    for (int e = gtid; e < E_SG; e += gs)
        atomicAdd(&g_deg[dst[e]], 1);
    if (gtid < 2) g_tctr[gtid] = 0;
    if (gtid <= ND) {
        if (gtid == ND) g_drug_start[ND] = N_SG;
        else {
            int lo = 0, hi = N_SG;
            while (lo < hi) {
                int mid = (lo + hi) >> 1;
                if (avgix[mid] < gtid) lo = mid + 1; else hi = mid;
            }
            g_drug_start[gtid] = lo;
        }
    }
    gridbar(gen0, 1);

    // ---- P1a: per-block chunk sums ----
    int* si = (int*)A;
    {
        int n0  = blockIdx.x * CHUNK;
        int len = NP - n0; if (len > CHUNK) len = CHUNK; if (len < 0) len = 0;
        int v = (tid < len) ? g_deg[n0 + tid] : 0;
        if (tid < CHUNK) si[tid] = v;
        __syncthreads();
        if (tid == 0) {
            int s = 0;
            for (int i = 0; i < len; i++) s += si[i];
            g_part[blockIdx.x] = s;
        }
    }
    gridbar(gen0, 2);

    // ---- P1b: block 0 scans the 148 partials ----
    if (blockIdx.x == 0) {
        int pv = (tid < NB) ? g_part[tid] : 0;
        if (tid < NB) si[tid] = pv;
        __syncthreads();
        if (tid == 0) {
            int run = 0;
            for (int i = 0; i < NB; i++) { int t = si[i]; si[i] = run; run += t; }
        }
        __syncthreads();
        if (tid < NB) g_poff[tid] = si[tid];
    }
    gridbar(gen0, 3);

    // ---- P1c: per-chunk prefix -> rowstart/fill/dinv ----
    {
        int n0  = blockIdx.x * CHUNK;
        int len = NP - n0; if (len > CHUNK) len = CHUNK; if (len < 0) len = 0;
        int v = (tid < len) ? g_deg[n0 + tid] : 0;
        if (tid < CHUNK) si[tid] = v;
        __syncthreads();
        if (tid == 0) {
            int run = g_poff[blockIdx.x];
            for (int i = 0; i < len; i++) { int t = si[i]; si[i] = run; run += t; }
        }
        __syncthreads();
        if (tid < len) {
            int node = n0 + tid;
            int rs = si[tid];
            g_rowstart[node] = rs;
            g_fill[node]     = rs;
            g_dinv[node]     = rsqrtf((float)v + 1.0f);
        }
        if (blockIdx.x == 0 && tid == 0) g_rowstart[NP] = E_SG;
    }
    gridbar(gen0, 4);

    // ---- P2: CSR fill + reset g_deg for next replay ----
    for (int e = gtid; e < E_SG; e += gs) {
        int d   = dst[e];
        int pos = atomicAdd(&g_fill[d], 1);
        g_csr_src[pos] = src[e];
    }
    for (int i = gtid; i < NP; i += gs) g_deg[i] = 0;
    gridbar(gen0, 5);

    // ---- P3: layer 1 ----
    layer_phase((const uint4*)g_xb, W1, b1, nullptr,
                (float4*)g_h1, (uint2*)g_h1b, true, 0, A, Bs, &s_tile);
    gridbar(gen0, 6);

    // ---- P4: layer 2 ----
    layer_phase((const uint4*)g_h1b, W2, b2, (const float4*)g_h1,
                nullptr, (uint2*)g_h2b, false, 1, A, Bs, &s_tile);
    gridbar(gen0, 7);

    // ---- P5: scatter-mean pooling from bf16 h2 ----
    {
        const uint4* h2b = (const uint4*)g_h2b;
        const ull one2 = pk(1.0f, 1.0f);
        for (int d = blockIdx.x; d < ND; d += NB) {
            int beg = g_drug_start[d];
            int end = g_drug_start[d + 1];
            ull a2[4] = {0ull, 0ull, 0ull, 0ull};
            for (int base = beg + wid * 32; base < end; base += NT) {
                int m = min(32, end - base);
                int nidx = 0;
                if (lane < m) nidx = nodes[base + lane] * 32;
                int k = 0;
                for (; k + 2 <= m; k += 2) {
                    int i0 = __shfl_sync(0xffffffffu, nidx, k);
                    int i1 = __shfl_sync(0xffffffffu, nidx, k + 1);
                    uint4 u0 = h2b[i0 + lane];
                    uint4 u1 = h2b[i1 + lane];
                    acc_row2(a2, u0, one2);
                    acc_row2(a2, u1, one2);
                }
                if (k < m) {
                    int i0 = __shfl_sync(0xffffffffu, nidx, k);
                    uint4 u0 = h2b[i0 + lane];
                    acc_row2(a2, u0, one2);
                }
            }
            __syncthreads();
            float* P = A;
            float2 f0 = upk(a2[0]), f1 = upk(a2[1]), f2 = upk(a2[2]), f3 = upk(a2[3]);
            *(float4*)&P[wid * 256 + lane * 8]     = make_float4(f0.x, f0.y, f1.x, f1.y);
            *(float4*)&P[wid * 256 + lane * 8 + 4] = make_float4(f2.x, f2.y, f3.x, f3.y);
            __syncthreads();
            if (tid < 256) {
                float s = 0.f;
                #pragma unroll
                for (int w = 0; w < NWARP; w++) s += P[w * 256 + tid];
                float inv = 1.0f / fmaxf((float)(end - beg), 1.0f);
                g_drug[d * 256 + tid] = s * inv;
            }
            __syncthreads();
        }
    }
    gridbar(gen0, 8);

    // ---- P6: prediction head ----
    {
        const float4* gd = (const float4*)g_drug;
        for (int p = blockIdx.x * NWARP + wid; p < B_DD; p += NB * NWARP) {
            int a = ddb[p];
            int b = ddb[B_DD + p];
            float4 va0 = gd[a * 64 + lane], va1 = gd[a * 64 + 32 + lane];
            float4 vb0 = gd[b * 64 + lane], vb1 = gd[b * 64 + 32 + lane];
            float s = va0.x * vb0.x + va0.y * vb0.y + va0.z * vb0.z + va0.w * vb0.w
                    + va1.x * vb1.x + va1.y * vb1.y + va1.z * vb1.z + va1.w * vb1.w;
            #pragma unroll
            for (int off = 16; off; off >>= 1)
                s += __shfl_down_sync(0xffffffffu, s, off);
            if (lane == 0) out[p] = s;
        }
    }
}

// ---------------- launch ----------------------------------------------------
extern "C" void kernel_launch(void* const* d_in, const int* in_sizes, int n_in,
                              void* d_out, int out_size) {
    const float* x     = (const float*)d_in[0];
    const int*   ddb   = (const int*)d_in[1];
    const int*   sg_ei = (const int*)d_in[4];
    const int*   nodes = (const int*)d_in[5];
    const int*   avgix = (const int*)d_in[6];
    const float* W1    = (const float*)d_in[7];
    const float* b1    = (const float*)d_in[8];
    const float* W2    = (const float*)d_in[9];
    const float* b2    = (const float*)d_in[10];
    float* out = (float*)d_out;

    const int smem_bytes = (64 * ASTR + 16 * 256) * (int)sizeof(float);  // 83968
    static bool attr_set = false;
    if (!attr_set) {
        cudaFuncSetAttribute(mega_kernel, cudaFuncAttributeMaxDynamicSharedMemorySize,
                             smem_bytes);
        attr_set = true;
    }

    mega_kernel<<<NB, NT, smem_bytes>>>(x, ddb, sg_ei, sg_ei + E_SG,
                                        nodes, avgix, W1, b1, W2, b2, out);
}

// round 9
// speedup vs baseline: 1.2502x; 1.2502x over previous
#include <cuda_runtime.h>
#include <cuda_bf16.h>

#define NP     19000
#define E_SG   1500000
#define N_SG   800000
#define ND     1024
#define B_DD   4096
#define NB     148
#define NT     512
#define NWARP  16
#define CHUNK  129
#define AST2   264          // A tile row stride in bf16 elems (528B = 33 x 16B units)
#define WST2   136          // Ws chunk row stride in bf16 elems (272B = 17 units)
#define NTILE  297

// ---------------- persistent device state -----------------------------------
__device__ float          g_h1[NP * 256];
__device__ unsigned       g_xb [NP * 128];
__device__ unsigned       g_h1b[NP * 128];
__device__ unsigned       g_h2b[NP * 128];
__device__ unsigned short g_w1t[256 * 256];   // W1^T bf16, n-major [n][k]
__device__ unsigned short g_w2t[256 * 256];   // W2^T bf16
__device__ float          g_dinv[NP];
__device__ int            g_deg[NP];
__device__ int            g_rowstart[NP + 1];
__device__ int            g_fill[NP];
__device__ int            g_csr_src[E_SG];
__device__ float          g_drug[ND * 256];
__device__ int            g_drug_start[ND + 1];
__device__ int            g_part[NB];
__device__ int            g_poff[NB];
__device__ int            g_tctr[2];
__device__ unsigned       g_cnt;
__device__ unsigned       g_gen;

__device__ __forceinline__ unsigned pack2(float a, float b) {
    __nv_bfloat162 t = __floats2bfloat162_rn(a, b);
    return *(unsigned*)&t;
}
__device__ __forceinline__ float2 unpack2(unsigned u) {
    return __bfloat1622float2(*(__nv_bfloat162*)&u);
}
__device__ __forceinline__ unsigned short b16(float f) {
    __nv_bfloat16 h = __float2bfloat16_rn(f);
    return *(unsigned short*)&h;
}
__device__ __forceinline__ unsigned smem_u32(const void* p) {
    unsigned a;
    asm("{ .reg .u64 t; cvta.to.shared.u64 t, %1; cvt.u32.u64 %0, t; }"
        : "=r"(a) : "l"(p));
    return a;
}
__device__ __forceinline__ void ldsm_x4(unsigned& r0, unsigned& r1, unsigned& r2,
                                        unsigned& r3, unsigned addr) {
    asm volatile("ldmatrix.sync.aligned.m8n8.x4.shared.b16 {%0,%1,%2,%3}, [%4];"
                 : "=r"(r0), "=r"(r1), "=r"(r2), "=r"(r3) : "r"(addr));
}
__device__ __forceinline__ void mma_bf16(float* c, unsigned a0, unsigned a1,
                                         unsigned a2, unsigned a3,
                                         unsigned b0, unsigned b1) {
    asm volatile(
        "mma.sync.aligned.m16n8k16.row.col.f32.bf16.bf16.f32 "
        "{%0,%1,%2,%3}, {%4,%5,%6,%7}, {%8,%9}, {%0,%1,%2,%3};"
        : "+f"(c[0]), "+f"(c[1]), "+f"(c[2]), "+f"(c[3])
        : "r"(a0), "r"(a1), "r"(a2), "r"(a3), "r"(b0), "r"(b1));
}

// Software grid barrier; all 148 blocks co-resident (1 block/SM).
__device__ __forceinline__ void gridbar(unsigned gen0, unsigned k) {
    __syncthreads();
    if (threadIdx.x == 0) {
        __threadfence();
        unsigned pos = atomicAdd(&g_cnt, 1u);
        if (pos == NB - 1u) {
            atomicExch(&g_cnt, 0u);
            __threadfence();
            atomicAdd(&g_gen, 1u);
        } else {
            unsigned target = gen0 + k;
            while ((int)(*(volatile unsigned*)&g_gen - target) < 0) __nanosleep(64);
        }
        __threadfence();
    }
    __syncthreads();
}

// accumulate one bf16 row (uint4 = 8 bf16) * w into a[8] (scalar fp32 FFMA)
__device__ __forceinline__ void acc_row(float* a, uint4 u, float w) {
    float2 f;
    f = unpack2(u.x); a[0] = fmaf(f.x, w, a[0]); a[1] = fmaf(f.y, w, a[1]);
    f = unpack2(u.y); a[2] = fmaf(f.x, w, a[2]); a[3] = fmaf(f.y, w, a[3]);
    f = unpack2(u.z); a[4] = fmaf(f.x, w, a[4]); a[5] = fmaf(f.y, w, a[5]);
    f = unpack2(u.w); a[6] = fmaf(f.x, w, a[6]); a[7] = fmaf(f.y, w, a[7]);
}

// ---------------- fused GCN layer: bf16 gather + HMMA GEMM ------------------
__device__ void layer_phase(const uint4* __restrict__ inb,
                            const unsigned short* __restrict__ Wt,
                            const float* __restrict__ bias,
                            const float* __restrict__ resid,
                            float* __restrict__ out_f32, unsigned* __restrict__ out_b16,
                            bool relu, int layer,
                            unsigned short* A_s, unsigned short* Ws, int* s_tile) {
    const int tid  = threadIdx.x;
    const int lane = tid & 31;
    const int wid  = tid >> 5;
    const unsigned baseA = smem_u32(A_s);
    const unsigned baseW = smem_u32(Ws);

    for (;;) {
        __syncthreads();
        if (tid == 0) *s_tile = atomicAdd(&g_tctr[layer], 1);
        __syncthreads();
        const int tile = *s_tile;
        if (tile >= NTILE) break;
        const int r0 = tile * 64;

        // ---- gather: warp wid produces rows wid*4 .. wid*4+3 (cols lane*8..+7)
        for (int i = 0; i < 4; i++) {
            int rr = wid * 4 + i;
            int r  = r0 + rr;
            float a[8] = {0.f, 0.f, 0.f, 0.f, 0.f, 0.f, 0.f, 0.f};
            if (r < NP) {
                int beg = g_rowstart[r];
                int end = g_rowstart[r + 1];
                for (int base = beg; base < end; base += 32) {
                    int m = min(32, end - base);
                    int sidx = 0; float sw = 0.f;
                    if (lane < m) {
                        int s = g_csr_src[base + lane];
                        sidx = s * 32;
                        sw   = g_dinv[s];
                    }
                    int k = 0;
                    for (; k + 4 <= m; k += 4) {
                        int   i0 = __shfl_sync(0xffffffffu, sidx, k);
                        float w0 = __shfl_sync(0xffffffffu, sw,   k);
                        int   i1 = __shfl_sync(0xffffffffu, sidx, k + 1);
                        float w1 = __shfl_sync(0xffffffffu, sw,   k + 1);
                        int   i2 = __shfl_sync(0xffffffffu, sidx, k + 2);
                        float w2 = __shfl_sync(0xffffffffu, sw,   k + 2);
                        int   i3 = __shfl_sync(0xffffffffu, sidx, k + 3);
                        float w3 = __shfl_sync(0xffffffffu, sw,   k + 3);
                        uint4 u0 = inb[i0 + lane];
                        uint4 u1 = inb[i1 + lane];
                        uint4 u2 = inb[i2 + lane];
                        uint4 u3 = inb[i3 + lane];
                        acc_row(a, u0, w0);
                        acc_row(a, u1, w1);
                        acc_row(a, u2, w2);
                        acc_row(a, u3, w3);
                    }
                    for (; k < m; k++) {
                        int   i0 = __shfl_sync(0xffffffffu, sidx, k);
                        float w0 = __shfl_sync(0xffffffffu, sw,   k);
                        uint4 u0 = inb[i0 + lane];
                        acc_row(a, u0, w0);
                    }
                }
                float di = g_dinv[r];
                uint4 us = inb[r * 32 + lane];
                float2 f;
                f = unpack2(us.x); a[0] = (a[0] + f.x * di) * di; a[1] = (a[1] + f.y * di) * di;
                f = unpack2(us.y); a[2] = (a[2] + f.x * di) * di; a[3] = (a[3] + f.y * di) * di;
                f = unpack2(us.z); a[4] = (a[4] + f.x * di) * di; a[5] = (a[5] + f.y * di) * di;
                f = unpack2(us.w); a[6] = (a[6] + f.x * di) * di; a[7] = (a[7] + f.y * di) * di;
            }
            uint4 pA;
            pA.x = pack2(a[0], a[1]); pA.y = pack2(a[2], a[3]);
            pA.z = pack2(a[4], a[5]); pA.w = pack2(a[6], a[7]);
            *(uint4*)&A_s[rr * AST2 + lane * 8] = pA;
        }
        __syncthreads();

        // ---- GEMM: H[64,256] = A_s(bf16) @ W(bf16) via mma.sync ----
        const int mg = wid & 3;          // m-group: rows mg*16..+15
        const int ng = wid >> 2;         // n-group: cols ng*64..+63
        const int g  = lane >> 3;        // ldmatrix lane-group
        float c[8][4];
        #pragma unroll
        for (int f = 0; f < 8; f++)
            #pragma unroll
            for (int q = 0; q < 4; q++) c[f][q] = 0.f;

        const int arow  = mg * 16 + (lane & 7) + (g & 1) * 8;
        const int akofs = (g >> 1) * 8;
        const unsigned aaddr0 = baseA + (unsigned)(arow * AST2 + akofs) * 2u;
        const int brow_base = ng * 64 + (lane & 7) + (g & 2) * 4;
        const int bkofs = (g & 1) * 8;

        #pragma unroll
        for (int kc = 0; kc < 2; kc++) {
            // stage W chunk: 256 n-rows x 128 k (bf16) -> Ws
            for (int i = tid; i < 4096; i += NT) {
                int n = i >> 4, o = i & 15;
                uint4 v = *(const uint4*)&Wt[n * 256 + kc * 128 + o * 8];
                *(uint4*)&Ws[n * WST2 + o * 8] = v;
            }
            __syncthreads();
            #pragma unroll
            for (int kk = 0; kk < 128; kk += 16) {
                unsigned a0, a1, a2, a3;
                ldsm_x4(a0, a1, a2, a3, aaddr0 + (unsigned)(kc * 128 + kk) * 2u);
                #pragma unroll
                for (int s = 0; s < 4; s++) {
                    unsigned baddr = baseW +
                        (unsigned)((brow_base + s * 16) * WST2 + kk + bkofs) * 2u;
                    unsigned b0, b1, b2, b3;
                    ldsm_x4(b0, b1, b2, b3, baddr);
                    mma_bf16(c[2 * s],     a0, a1, a2, a3, b0, b1);
                    mma_bf16(c[2 * s + 1], a0, a1, a2, a3, b2, b3);
                }
            }
            __syncthreads();
        }

        // ---- epilogue: bias (+residual) (+relu) -> fp32 / bf16 ----
        const int gr   = lane >> 2;
        const int colq = (lane & 3) * 2;
        #pragma unroll
        for (int f = 0; f < 8; f++) {
            int col = ng * 64 + f * 8 + colq;
            float2 bi = *(const float2*)&bias[col];
            #pragma unroll
            for (int half = 0; half < 2; half++) {
                int r = r0 + mg * 16 + gr + half * 8;
                if (r < NP) {
                    float vx = c[f][2 * half]     + bi.x;
                    float vy = c[f][2 * half + 1] + bi.y;
                    if (resid) {
                        float2 rr2 = *(const float2*)&resid[r * 256 + col];
                        vx += rr2.x; vy += rr2.y;
                    }
                    if (relu) { vx = fmaxf(vx, 0.f); vy = fmaxf(vy, 0.f); }
                    if (out_f32) {
                        float2 o; o.x = vx; o.y = vy;
                        *(float2*)&out_f32[r * 256 + col] = o;
                    }
                    if (out_b16) out_b16[r * 128 + (col >> 1)] = pack2(vx, vy);
                }
            }
        }
    }
}

// ---------------- the single mega-kernel ------------------------------------
__global__ __launch_bounds__(NT, 1) void mega_kernel(
    const float* __restrict__ x, const int* __restrict__ ddb,
    const int* __restrict__ src, const int* __restrict__ dst,
    const int* __restrict__ nodes, const int* __restrict__ avgix,
    const float* __restrict__ W1, const float* __restrict__ b1,
    const float* __restrict__ W2, const float* __restrict__ b2,
    float* __restrict__ out)
{
    extern __shared__ char smem_raw[];
    unsigned short* A_s = (unsigned short*)smem_raw;              // 64*264*2  = 33792B
    unsigned short* Ws  = (unsigned short*)(smem_raw + 33792);    // 256*136*2 = 69632B
    __shared__ unsigned s_gen0;
    __shared__ int s_tile;

    const int tid  = threadIdx.x;
    const int lane = tid & 31;
    const int wid  = tid >> 5;
    const int gtid = blockIdx.x * NT + tid;
    const int gs   = NB * NT;

    if (tid == 0) s_gen0 = *(volatile unsigned*)&g_gen;
    __syncthreads();
    const unsigned gen0 = s_gen0;

    // ---- P0: x->bf16, W->bf16^T, histogram, drug bounds, counters ----
    {
        const float2* x2 = (const float2*)x;
        for (int i = gtid; i < NP * 128; i += gs) {
            float2 v = x2[i];
            g_xb[i] = pack2(v.x, v.y);
        }
        for (int i = gtid; i < 256 * 256; i += gs) {
            int n = i >> 8, k = i & 255;
            g_w1t[i] = b16(W1[k * 256 + n]);
            g_w2t[i] = b16(W2[k * 256 + n]);
        }
    }
    for (int e = gtid; e < E_SG; e += gs)
        atomicAdd(&g_deg[dst[e]], 1);
    if (gtid < 2) g_tctr[gtid] = 0;
    if (gtid <= ND) {
        if (gtid == ND) g_drug_start[ND] = N_SG;
        else {
            int lo = 0, hi = N_SG;
            while (lo < hi) {
                int mid = (lo + hi) >> 1;
                if (avgix[mid] < gtid) lo = mid + 1; else hi = mid;
            }
            g_drug_start[gtid] = lo;
        }
    }
    gridbar(gen0, 1);

    // ---- P1a: per-block chunk sums ----
    int* si = (int*)smem_raw;
    {
        int n0  = blockIdx.x * CHUNK;
        int len = NP - n0; if (len > CHUNK) len = CHUNK; if (len < 0) len = 0;
        int v = (tid < len) ? g_deg[n0 + tid] : 0;
        if (tid < CHUNK) si[tid] = v;
        __syncthreads();
        if (tid == 0) {
            int s = 0;
            for (int i = 0; i < len; i++) s += si[i];
            g_part[blockIdx.x] = s;
        }
    }
    gridbar(gen0, 2);

    // ---- P1b: block 0 scans the 148 partials ----
    if (blockIdx.x == 0) {
        int pv = (tid < NB) ? g_part[tid] : 0;
        if (tid < NB) si[tid] = pv;
        __syncthreads();
        if (tid == 0) {
            int run = 0;
            for (int i = 0; i < NB; i++) { int t = si[i]; si[i] = run; run += t; }
        }
        __syncthreads();
        if (tid < NB) g_poff[tid] = si[tid];
    }
    gridbar(gen0, 3);

    // ---- P1c: per-chunk prefix -> rowstart/fill/dinv ----
    {
        int n0  = blockIdx.x * CHUNK;
        int len = NP - n0; if (len > CHUNK) len = CHUNK; if (len < 0) len = 0;
        int v = (tid < len) ? g_deg[n0 + tid] : 0;
        if (tid < CHUNK) si[tid] = v;
        __syncthreads();
        if (tid == 0) {
            int run = g_poff[blockIdx.x];
            for (int i = 0; i < len; i++) { int t = si[i]; si[i] = run; run += t; }
        }
        __syncthreads();
        if (tid < len) {
            int node = n0 + tid;
            int rs = si[tid];
            g_rowstart[node] = rs;
            g_fill[node]     = rs;
            g_dinv[node]     = rsqrtf((float)v + 1.0f);
        }
        if (blockIdx.x == 0 && tid == 0) g_rowstart[NP] = E_SG;
    }
    gridbar(gen0, 4);

    // ---- P2: CSR fill + reset g_deg ----
    for (int e = gtid; e < E_SG; e += gs) {
        int d   = dst[e];
        int pos = atomicAdd(&g_fill[d], 1);
        g_csr_src[pos] = src[e];
    }
    for (int i = gtid; i < NP; i += gs) g_deg[i] = 0;
    gridbar(gen0, 5);

    // ---- P3: layer 1  h1 = relu(agg(xb) @ W1 + b1) -> fp32 + bf16 ----
    layer_phase((const uint4*)g_xb, g_w1t, b1, nullptr,
                g_h1, g_h1b, true, 0, A_s, Ws, &s_tile);
    gridbar(gen0, 6);

    // ---- P4: layer 2  h2 = agg(h1b) @ W2 + b2 + h1 -> bf16 only ----
    layer_phase((const uint4*)g_h1b, g_w2t, b2, g_h1,
                nullptr, g_h2b, false, 1, A_s, Ws, &s_tile);
    gridbar(gen0, 7);

    // ---- P5: scatter-mean pooling from bf16 h2 ----
    {
        const uint4* h2b = (const uint4*)g_h2b;
        float* P = (float*)smem_raw;        // 16 warps x 256 floats = 16KB
        for (int d = blockIdx.x; d < ND; d += NB) {
            int beg = g_drug_start[d];
            int end = g_drug_start[d + 1];
            float a[8] = {0.f, 0.f, 0.f, 0.f, 0.f, 0.f, 0.f, 0.f};
            for (int base = beg + wid * 32; base < end; base += NT) {
                int m = min(32, end - base);
                int nidx = 0;
                if (lane < m) nidx = nodes[base + lane] * 32;
                int k = 0;
                for (; k + 2 <= m; k += 2) {
                    int i0 = __shfl_sync(0xffffffffu, nidx, k);
                    int i1 = __shfl_sync(0xffffffffu, nidx, k + 1);
                    uint4 u0 = h2b[i0 + lane];
                    uint4 u1 = h2b[i1 + lane];
                    acc_row(a, u0, 1.0f);
                    acc_row(a, u1, 1.0f);
                }
                if (k < m) {
                    int i0 = __shfl_sync(0xffffffffu, nidx, k);
                    uint4 u0 = h2b[i0 + lane];
                    acc_row(a, u0, 1.0f);
                }
            }
            __syncthreads();
            *(float4*)&P[wid * 256 + lane * 8]     = make_float4(a[0], a[1], a[2], a[3]);
            *(float4*)&P[wid * 256 + lane * 8 + 4] = make_float4(a[4], a[5], a[6], a[7]);
            __syncthreads();
            if (tid < 256) {
                float s = 0.f;
                #pragma unroll
                for (int w = 0; w < NWARP; w++) s += P[w * 256 + tid];
                float inv = 1.0f / fmaxf((float)(end - beg), 1.0f);
                g_drug[d * 256 + tid] = s * inv;
            }
            __syncthreads();
        }
    }
    gridbar(gen0, 8);

    // ---- P6: prediction head ----
    {
        const float4* gd = (const float4*)g_drug;
        for (int p = blockIdx.x * NWARP + wid; p < B_DD; p += NB * NWARP) {
            int a = ddb[p];
            int b = ddb[B_DD + p];
            float4 va0 = gd[a * 64 + lane], va1 = gd[a * 64 + 32 + lane];
            float4 vb0 = gd[b * 64 + lane], vb1 = gd[b * 64 + 32 + lane];
            float s = va0.x * vb0.x + va0.y * vb0.y + va0.z * vb0.z + va0.w * vb0.w
                    + va1.x * vb1.x + va1.y * vb1.y + va1.z * vb1.z + va1.w * vb1.w;
            #pragma unroll
            for (int off = 16; off; off >>= 1)
                s += __shfl_down_sync(0xffffffffu, s, off);
            if (lane == 0) out[p] = s;
        }
    }
}

// ---------------- launch ----------------------------------------------------
extern "C" void kernel_launch(void* const* d_in, const int* in_sizes, int n_in,
                              void* d_out, int out_size) {
    const float* x     = (const float*)d_in[0];
    const int*   ddb   = (const int*)d_in[1];
    const int*   sg_ei = (const int*)d_in[4];
    const int*   nodes = (const int*)d_in[5];
    const int*   avgix = (const int*)d_in[6];
    const float* W1    = (const float*)d_in[7];
    const float* b1    = (const float*)d_in[8];
    const float* W2    = (const float*)d_in[9];
    const float* b2    = (const float*)d_in[10];
    float* out = (float*)d_out;

    const int smem_bytes = 33792 + 69632;   // A_s + Ws = 103424
    static bool attr_set = false;
    if (!attr_set) {
        cudaFuncSetAttribute(mega_kernel, cudaFuncAttributeMaxDynamicSharedMemorySize,
                             smem_bytes);
        attr_set = true;
    }

    mega_kernel<<<NB, NT, smem_bytes>>>(x, ddb, sg_ei, sg_ei + E_SG,
                                        nodes, avgix, W1, b1, W2, b2, out);
}

// round 10
// speedup vs baseline: 1.8453x; 1.4760x over previous
#include <cuda_runtime.h>
#include <cuda_bf16.h>

#define NP     19000
#define E_SG   1500000
#define N_SG   800000
#define ND     1024
#define B_DD   4096
#define NB     148
#define NT     512
#define NWARP  16
#define CHUNK  129
#define AST2   264          // A tile row stride in bf16 elems (528B; 528%128=16 -> conflict-free)
#define WST2   264          // Ws row stride in bf16 elems (528B)
#define NTILE  297

// ---------------- persistent device state -----------------------------------
__device__ float          g_h1[NP * 256];
__device__ unsigned       g_xb [NP * 128];
__device__ unsigned       g_h1b[NP * 128];
__device__ unsigned       g_h2b[NP * 128];
__device__ unsigned short g_w1t[256 * 256];   // W1^T bf16, n-major [n][k]
__device__ unsigned short g_w2t[256 * 256];   // W2^T bf16
__device__ float          g_dinv[NP];
__device__ int            g_deg[NP];
__device__ int            g_rowstart[NP + 1];
__device__ int            g_fill[NP];
__device__ int            g_csr_src[E_SG];
__device__ float          g_drug[ND * 256];
__device__ int            g_drug_start[ND + 1];
__device__ int            g_part[NB];
__device__ int            g_poff[NB];
__device__ int            g_tctr[2];
__device__ unsigned       g_cnt;
__device__ unsigned       g_gen;

__device__ __forceinline__ unsigned pack2(float a, float b) {
    __nv_bfloat162 t = __floats2bfloat162_rn(a, b);
    return *(unsigned*)&t;
}
__device__ __forceinline__ float2 unpack2(unsigned u) {
    return __bfloat1622float2(*(__nv_bfloat162*)&u);
}
__device__ __forceinline__ unsigned short b16(float f) {
    __nv_bfloat16 h = __float2bfloat16_rn(f);
    return *(unsigned short*)&h;
}
__device__ __forceinline__ unsigned smem_u32(const void* p) {
    unsigned a;
    asm("{ .reg .u64 t; cvta.to.shared.u64 t, %1; cvt.u32.u64 %0, t; }"
        : "=r"(a) : "l"(p));
    return a;
}
__device__ __forceinline__ void ldsm_x4(unsigned& r0, unsigned& r1, unsigned& r2,
                                        unsigned& r3, unsigned addr) {
    asm volatile("ldmatrix.sync.aligned.m8n8.x4.shared.b16 {%0,%1,%2,%3}, [%4];"
                 : "=r"(r0), "=r"(r1), "=r"(r2), "=r"(r3) : "r"(addr));
}
__device__ __forceinline__ void mma_bf16(float* c, unsigned a0, unsigned a1,
                                         unsigned a2, unsigned a3,
                                         unsigned b0, unsigned b1) {
    asm volatile(
        "mma.sync.aligned.m16n8k16.row.col.f32.bf16.bf16.f32 "
        "{%0,%1,%2,%3}, {%4,%5,%6,%7}, {%8,%9}, {%0,%1,%2,%3};"
        : "+f"(c[0]), "+f"(c[1]), "+f"(c[2]), "+f"(c[3])
        : "r"(a0), "r"(a1), "r"(a2), "r"(a3), "r"(b0), "r"(b1));
}

// Software grid barrier; all 148 blocks co-resident (1 block/SM).
__device__ __forceinline__ void gridbar(unsigned gen0, unsigned k) {
    __syncthreads();
    if (threadIdx.x == 0) {
        __threadfence();
        unsigned pos = atomicAdd(&g_cnt, 1u);
        if (pos == NB - 1u) {
            atomicExch(&g_cnt, 0u);
            __threadfence();
            atomicAdd(&g_gen, 1u);
        } else {
            unsigned target = gen0 + k;
            while ((int)(*(volatile unsigned*)&g_gen - target) < 0) __nanosleep(64);
        }
        __threadfence();
    }
    __syncthreads();
}

// accumulate one bf16 row (uint4 = 8 bf16) * w into a[8] (scalar fp32 FFMA)
__device__ __forceinline__ void acc_row(float* a, uint4 u, float w) {
    float2 f;
    f = unpack2(u.x); a[0] = fmaf(f.x, w, a[0]); a[1] = fmaf(f.y, w, a[1]);
    f = unpack2(u.y); a[2] = fmaf(f.x, w, a[2]); a[3] = fmaf(f.y, w, a[3]);
    f = unpack2(u.z); a[4] = fmaf(f.x, w, a[4]); a[5] = fmaf(f.y, w, a[5]);
    f = unpack2(u.w); a[6] = fmaf(f.x, w, a[6]); a[7] = fmaf(f.y, w, a[7]);
}

// ---------------- fused GCN layer: bf16 gather + HMMA GEMM (W smem-resident)
__device__ void layer_phase(const uint4* __restrict__ inb,
                            const unsigned short* __restrict__ Wt,
                            const float* __restrict__ bias,
                            const float* __restrict__ resid,
                            float* __restrict__ out_f32, unsigned* __restrict__ out_b16,
                            bool relu, int layer,
                            unsigned short* A_s, unsigned short* Ws, int* s_tile) {
    const int tid  = threadIdx.x;
    const int lane = tid & 31;
    const int wid  = tid >> 5;
    const unsigned baseA = smem_u32(A_s);
    const unsigned baseW = smem_u32(Ws);

    // ---- stage FULL W (256x256 bf16) into smem once per layer ----
    for (int i = tid; i < 8192; i += NT) {       // 8192 uint4 = 256 rows x 32
        int n = i >> 5, o = i & 31;
        uint4 v = *(const uint4*)&Wt[n * 256 + o * 8];
        *(uint4*)&Ws[n * WST2 + o * 8] = v;
    }
    __syncthreads();

    for (;;) {
        __syncthreads();
        if (tid == 0) *s_tile = atomicAdd(&g_tctr[layer], 1);
        __syncthreads();
        const int tile = *s_tile;
        if (tile >= NTILE) break;
        const int r0 = tile * 64;

        // ---- gather: warp wid produces rows wid*4 .. wid*4+3 (cols lane*8..+7)
        for (int i = 0; i < 4; i++) {
            int rr = wid * 4 + i;
            int r  = r0 + rr;
            float a[8] = {0.f, 0.f, 0.f, 0.f, 0.f, 0.f, 0.f, 0.f};
            if (r < NP) {
                int beg = g_rowstart[r];
                int end = g_rowstart[r + 1];
                for (int base = beg; base < end; base += 32) {
                    int m = min(32, end - base);
                    int sidx = 0; float sw = 0.f;
                    if (lane < m) {
                        int s = g_csr_src[base + lane];
                        sidx = s * 32;
                        sw   = g_dinv[s];
                    }
                    int k = 0;
                    for (; k + 4 <= m; k += 4) {
                        int   i0 = __shfl_sync(0xffffffffu, sidx, k);
                        float w0 = __shfl_sync(0xffffffffu, sw,   k);
                        int   i1 = __shfl_sync(0xffffffffu, sidx, k + 1);
                        float w1 = __shfl_sync(0xffffffffu, sw,   k + 1);
                        int   i2 = __shfl_sync(0xffffffffu, sidx, k + 2);
                        float w2 = __shfl_sync(0xffffffffu, sw,   k + 2);
                        int   i3 = __shfl_sync(0xffffffffu, sidx, k + 3);
                        float w3 = __shfl_sync(0xffffffffu, sw,   k + 3);
                        uint4 u0 = inb[i0 + lane];
                        uint4 u1 = inb[i1 + lane];
                        uint4 u2 = inb[i2 + lane];
                        uint4 u3 = inb[i3 + lane];
                        acc_row(a, u0, w0);
                        acc_row(a, u1, w1);
                        acc_row(a, u2, w2);
                        acc_row(a, u3, w3);
                    }
                    for (; k < m; k++) {
                        int   i0 = __shfl_sync(0xffffffffu, sidx, k);
                        float w0 = __shfl_sync(0xffffffffu, sw,   k);
                        uint4 u0 = inb[i0 + lane];
                        acc_row(a, u0, w0);
                    }
                }
                float di = g_dinv[r];
                uint4 us = inb[r * 32 + lane];
                float2 f;
                f = unpack2(us.x); a[0] = (a[0] + f.x * di) * di; a[1] = (a[1] + f.y * di) * di;
                f = unpack2(us.y); a[2] = (a[2] + f.x * di) * di; a[3] = (a[3] + f.y * di) * di;
                f = unpack2(us.z); a[4] = (a[4] + f.x * di) * di; a[5] = (a[5] + f.y * di) * di;
                f = unpack2(us.w); a[6] = (a[6] + f.x * di) * di; a[7] = (a[7] + f.y * di) * di;
            }
            uint4 pA;
            pA.x = pack2(a[0], a[1]); pA.y = pack2(a[2], a[3]);
            pA.z = pack2(a[4], a[5]); pA.w = pack2(a[6], a[7]);
            *(uint4*)&A_s[rr * AST2 + lane * 8] = pA;
        }
        __syncthreads();

        // ---- GEMM: H[64,256] = A_s(bf16) @ W(bf16) via mma.sync, W resident
        const int mg = wid & 3;          // m-group: rows mg*16..+15
        const int ng = wid >> 2;         // n-group: cols ng*64..+63
        const int g  = lane >> 3;        // ldmatrix lane-group
        float c[8][4];
        #pragma unroll
        for (int f = 0; f < 8; f++)
            #pragma unroll
            for (int q = 0; q < 4; q++) c[f][q] = 0.f;

        const int arow  = mg * 16 + (lane & 7) + (g & 1) * 8;
        const int akofs = (g >> 1) * 8;
        const unsigned aaddr0 = baseA + (unsigned)(arow * AST2 + akofs) * 2u;
        const int brow_base = ng * 64 + (lane & 7) + (g & 2) * 4;
        const int bkofs = (g & 1) * 8;

        #pragma unroll
        for (int kk = 0; kk < 256; kk += 16) {
            unsigned a0, a1, a2, a3;
            ldsm_x4(a0, a1, a2, a3, aaddr0 + (unsigned)kk * 2u);
            #pragma unroll
            for (int s = 0; s < 4; s++) {
                unsigned baddr = baseW +
                    (unsigned)((brow_base + s * 16) * WST2 + kk + bkofs) * 2u;
                unsigned b0, b1, b2, b3;
                ldsm_x4(b0, b1, b2, b3, baddr);
                mma_bf16(c[2 * s],     a0, a1, a2, a3, b0, b1);
                mma_bf16(c[2 * s + 1], a0, a1, a2, a3, b2, b3);
            }
        }

        // ---- epilogue: bias (+residual) (+relu) -> fp32 / bf16 ----
        const int gr   = lane >> 2;
        const int colq = (lane & 3) * 2;
        #pragma unroll
        for (int f = 0; f < 8; f++) {
            int col = ng * 64 + f * 8 + colq;
            float2 bi = *(const float2*)&bias[col];
            #pragma unroll
            for (int half = 0; half < 2; half++) {
                int r = r0 + mg * 16 + gr + half * 8;
                if (r < NP) {
                    float vx = c[f][2 * half]     + bi.x;
                    float vy = c[f][2 * half + 1] + bi.y;
                    if (resid) {
                        float2 rr2 = *(const float2*)&resid[r * 256 + col];
                        vx += rr2.x; vy += rr2.y;
                    }
                    if (relu) { vx = fmaxf(vx, 0.f); vy = fmaxf(vy, 0.f); }
                    if (out_f32) {
                        float2 o; o.x = vx; o.y = vy;
                        *(float2*)&out_f32[r * 256 + col] = o;
                    }
                    if (out_b16) out_b16[r * 128 + (col >> 1)] = pack2(vx, vy);
                }
            }
        }
    }
}

// ---------------- the single mega-kernel ------------------------------------
__global__ __launch_bounds__(NT, 1) void mega_kernel(
    const float* __restrict__ x, const int* __restrict__ ddb,
    const int* __restrict__ src, const int* __restrict__ dst,
    const int* __restrict__ nodes, const int* __restrict__ avgix,
    const float* __restrict__ W1, const float* __restrict__ b1,
    const float* __restrict__ W2, const float* __restrict__ b2,
    float* __restrict__ out)
{
    extern __shared__ char smem_raw[];
    unsigned short* A_s = (unsigned short*)smem_raw;              // 64*264*2  = 33792B
    unsigned short* Ws  = (unsigned short*)(smem_raw + 33792);    // 256*264*2 = 135168B
    __shared__ unsigned s_gen0;
    __shared__ int s_tile;

    const int tid  = threadIdx.x;
    const int lane = tid & 31;
    const int wid  = tid >> 5;
    const int gtid = blockIdx.x * NT + tid;
    const int gs   = NB * NT;

    if (tid == 0) s_gen0 = *(volatile unsigned*)&g_gen;
    __syncthreads();
    const unsigned gen0 = s_gen0;

    // ---- P0: x->bf16, W->bf16^T, histogram, drug bounds, counters ----
    {
        const float2* x2 = (const float2*)x;
        for (int i = gtid; i < NP * 128; i += gs) {
            float2 v = x2[i];
            g_xb[i] = pack2(v.x, v.y);
        }
        for (int i = gtid; i < 256 * 256; i += gs) {
            int n = i >> 8, k = i & 255;
            g_w1t[i] = b16(W1[k * 256 + n]);
            g_w2t[i] = b16(W2[k * 256 + n]);
        }
    }
    for (int e = gtid; e < E_SG; e += gs)
        atomicAdd(&g_deg[dst[e]], 1);
    if (gtid < 2) g_tctr[gtid] = 0;
    if (gtid <= ND) {
        if (gtid == ND) g_drug_start[ND] = N_SG;
        else {
            int lo = 0, hi = N_SG;
            while (lo < hi) {
                int mid = (lo + hi) >> 1;
                if (avgix[mid] < gtid) lo = mid + 1; else hi = mid;
            }
            g_drug_start[gtid] = lo;
        }
    }
    gridbar(gen0, 1);

    // ---- P1a: per-block chunk sums ----
    int* si = (int*)smem_raw;
    {
        int n0  = blockIdx.x * CHUNK;
        int len = NP - n0; if (len > CHUNK) len = CHUNK; if (len < 0) len = 0;
        int v = (tid < len) ? g_deg[n0 + tid] : 0;
        if (tid < CHUNK) si[tid] = v;
        __syncthreads();
        if (tid == 0) {
            int s = 0;
            for (int i = 0; i < len; i++) s += si[i];
            g_part[blockIdx.x] = s;
        }
    }
    gridbar(gen0, 2);

    // ---- P1b: block 0 scans the 148 partials ----
    if (blockIdx.x == 0) {
        int pv = (tid < NB) ? g_part[tid] : 0;
        if (tid < NB) si[tid] = pv;
        __syncthreads();
        if (tid == 0) {
            int run = 0;
            for (int i = 0; i < NB; i++) { int t = si[i]; si[i] = run; run += t; }
        }
        __syncthreads();
        if (tid < NB) g_poff[tid] = si[tid];
    }
    gridbar(gen0, 3);

    // ---- P1c: per-chunk prefix -> rowstart/fill/dinv ----
    {
        int n0  = blockIdx.x * CHUNK;
        int len = NP - n0; if (len > CHUNK) len = CHUNK; if (len < 0) len = 0;
        int v = (tid < len) ? g_deg[n0 + tid] : 0;
        if (tid < CHUNK) si[tid] = v;
        __syncthreads();
        if (tid == 0) {
            int run = g_poff[blockIdx.x];
            for (int i = 0; i < len; i++) { int t = si[i]; si[i] = run; run += t; }
        }
        __syncthreads();
        if (tid < len) {
            int node = n0 + tid;
            int rs = si[tid];
            g_rowstart[node] = rs;
            g_fill[node]     = rs;
            g_dinv[node]     = rsqrtf((float)v + 1.0f);
        }
        if (blockIdx.x == 0 && tid == 0) g_rowstart[NP] = E_SG;
    }
    gridbar(gen0, 4);

    // ---- P2: CSR fill + reset g_deg ----
    for (int e = gtid; e < E_SG; e += gs) {
        int d   = dst[e];
        int pos = atomicAdd(&g_fill[d], 1);
        g_csr_src[pos] = src[e];
    }
    for (int i = gtid; i < NP; i += gs) g_deg[i] = 0;
    gridbar(gen0, 5);

    // ---- P3: layer 1  h1 = relu(agg(xb) @ W1 + b1) -> fp32 + bf16 ----
    layer_phase((const uint4*)g_xb, g_w1t, b1, nullptr,
                g_h1, g_h1b, true, 0, A_s, Ws, &s_tile);
    gridbar(gen0, 6);

    // ---- P4: layer 2  h2 = agg(h1b) @ W2 + b2 + h1 -> bf16 only ----
    layer_phase((const uint4*)g_h1b, g_w2t, b2, g_h1,
                nullptr, g_h2b, false, 1, A_s, Ws, &s_tile);
    gridbar(gen0, 7);

    // ---- P5: scatter-mean pooling from bf16 h2 ----
    {
        const uint4* h2b = (const uint4*)g_h2b;
        float* P = (float*)smem_raw;        // 16 warps x 256 floats = 16KB
        for (int d = blockIdx.x; d < ND; d += NB) {
            int beg = g_drug_start[d];
            int end = g_drug_start[d + 1];
            float a[8] = {0.f, 0.f, 0.f, 0.f, 0.f, 0.f, 0.f, 0.f};
            for (int base = beg + wid * 32; base < end; base += NT) {
                int m = min(32, end - base);
                int nidx = 0;
                if (lane < m) nidx = nodes[base + lane] * 32;
                int k = 0;
                for (; k + 2 <= m; k += 2) {
                    int i0 = __shfl_sync(0xffffffffu, nidx, k);
                    int i1 = __shfl_sync(0xffffffffu, nidx, k + 1);
                    uint4 u0 = h2b[i0 + lane];
                    uint4 u1 = h2b[i1 + lane];
                    acc_row(a, u0, 1.0f);
                    acc_row(a, u1, 1.0f);
                }
                if (k < m) {
                    int i0 = __shfl_sync(0xffffffffu, nidx, k);
                    uint4 u0 = h2b[i0 + lane];
                    acc_row(a, u0, 1.0f);
                }
            }
            __syncthreads();
            *(float4*)&P[wid * 256 + lane * 8]     = make_float4(a[0], a[1], a[2], a[3]);
            *(float4*)&P[wid * 256 + lane * 8 + 4] = make_float4(a[4], a[5], a[6], a[7]);
            __syncthreads();
            if (tid < 256) {
                float s = 0.f;
                #pragma unroll
                for (int w = 0; w < NWARP; w++) s += P[w * 256 + tid];
                float inv = 1.0f / fmaxf((float)(end - beg), 1.0f);
                g_drug[d * 256 + tid] = s * inv;
            }
            __syncthreads();
        }
    }
    gridbar(gen0, 8);

    // ---- P6: prediction head ----
    {
        const float4* gd = (const float4*)g_drug;
        for (int p = blockIdx.x * NWARP + wid; p < B_DD; p += NB * NWARP) {
            int a = ddb[p];
            int b = ddb[B_DD + p];
            float4 va0 = gd[a * 64 + lane], va1 = gd[a * 64 + 32 + lane];
            float4 vb0 = gd[b * 64 + lane], vb1 = gd[b * 64 + 32 + lane];
            float s = va0.x * vb0.x + va0.y * vb0.y + va0.z * vb0.z + va0.w * vb0.w
                    + va1.x * vb1.x + va1.y * vb1.y + va1.z * vb1.z + va1.w * vb1.w;
            #pragma unroll
            for (int off = 16; off; off >>= 1)
                s += __shfl_down_sync(0xffffffffu, s, off);
            if (lane == 0) out[p] = s;
        }
    }
}

// ---------------- launch ----------------------------------------------------
extern "C" void kernel_launch(void* const* d_in, const int* in_sizes, int n_in,
                              void* d_out, int out_size) {
    const float* x     = (const float*)d_in[0];
    const int*   ddb   = (const int*)d_in[1];
    const int*   sg_ei = (const int*)d_in[4];
    const int*   nodes = (const int*)d_in[5];
    const int*   avgix = (const int*)d_in[6];
    const float* W1    = (const float*)d_in[7];
    const float* b1    = (const float*)d_in[8];
    const float* W2    = (const float*)d_in[9];
    const float* b2    = (const float*)d_in[10];
    float* out = (float*)d_out;

    const int smem_bytes = 33792 + 135168;   // A_s + full Ws = 168960
    static bool attr_set = false;
    if (!attr_set) {
        cudaFuncSetAttribute(mega_kernel, cudaFuncAttributeMaxDynamicSharedMemorySize,
                             smem_bytes);
        attr_set = true;
    }

    mega_kernel<<<NB, NT, smem_bytes>>>(x, ddb, sg_ei, sg_ei + E_SG,
                                        nodes, avgix, W1, b1, W2, b2, out);
}

// round 11
// speedup vs baseline: 1.8747x; 1.0159x over previous
#include <cuda_runtime.h>
#include <cuda_bf16.h>

#define NP     19000
#define E_SG   1500000
#define N_SG   800000
#define ND     1024
#define B_DD   4096
#define NB     148
#define NT     512
#define NWARP  16
#define CHUNK  129
#define AST2   264          // A tile row stride in bf16 elems (528B; %128=16 -> conflict-free)
#define WST2   264          // Ws row stride in bf16 elems
#define NTILE  297

// ---------------- persistent device state -----------------------------------
__device__ unsigned       g_xb  [NP * 128];   // dinv-prescaled x, bf16x2
__device__ unsigned       g_h1b [NP * 128];   // plain h1, bf16x2 (residual)
__device__ unsigned       g_h1sb[NP * 128];   // dinv-prescaled h1, bf16x2 (gather L2)
__device__ unsigned       g_h2b [NP * 128];   // plain h2, bf16x2 (pool)
__device__ unsigned short g_w1t[256 * 256];   // W1^T bf16, n-major [n][k]
__device__ unsigned short g_w2t[256 * 256];
__device__ float          g_dinv[NP];
__device__ int            g_deg[NP];
__device__ int            g_rowstart[NP + 1];
__device__ int            g_fill[NP];
__device__ int            g_csr_src[E_SG];
__device__ float          g_drug[ND * 256];
__device__ int            g_drug_start[ND + 1];
__device__ int            g_part[NB];
__device__ int            g_poff[NB];
__device__ int            g_tctr[2];
__device__ unsigned       g_cnt;
__device__ unsigned       g_gen;

__device__ __forceinline__ unsigned pack2(float a, float b) {
    __nv_bfloat162 t = __floats2bfloat162_rn(a, b);
    return *(unsigned*)&t;
}
__device__ __forceinline__ float2 unpack2(unsigned u) {
    return __bfloat1622float2(*(__nv_bfloat162*)&u);
}
__device__ __forceinline__ unsigned short b16(float f) {
    __nv_bfloat16 h = __float2bfloat16_rn(f);
    return *(unsigned short*)&h;
}
__device__ __forceinline__ unsigned smem_u32(const void* p) {
    unsigned a;
    asm("{ .reg .u64 t; cvta.to.shared.u64 t, %1; cvt.u32.u64 %0, t; }"
        : "=r"(a) : "l"(p));
    return a;
}
__device__ __forceinline__ void ldsm_x4(unsigned& r0, unsigned& r1, unsigned& r2,
                                        unsigned& r3, unsigned addr) {
    asm volatile("ldmatrix.sync.aligned.m8n8.x4.shared.b16 {%0,%1,%2,%3}, [%4];"
                 : "=r"(r0), "=r"(r1), "=r"(r2), "=r"(r3) : "r"(addr));
}
__device__ __forceinline__ void mma_bf16(float* c, unsigned a0, unsigned a1,
                                         unsigned a2, unsigned a3,
                                         unsigned b0, unsigned b1) {
    asm volatile(
        "mma.sync.aligned.m16n8k16.row.col.f32.bf16.bf16.f32 "
        "{%0,%1,%2,%3}, {%4,%5,%6,%7}, {%8,%9}, {%0,%1,%2,%3};"
        : "+f"(c[0]), "+f"(c[1]), "+f"(c[2]), "+f"(c[3])
        : "r"(a0), "r"(a1), "r"(a2), "r"(a3), "r"(b0), "r"(b1));
}

// Software grid barrier; all 148 blocks co-resident (1 block/SM).
__device__ __forceinline__ void gridbar(unsigned gen0, unsigned k) {
    __syncthreads();
    if (threadIdx.x == 0) {
        __threadfence();
        unsigned pos = atomicAdd(&g_cnt, 1u);
        if (pos == NB - 1u) {
            atomicExch(&g_cnt, 0u);
            __threadfence();
            atomicAdd(&g_gen, 1u);
        } else {
            unsigned target = gen0 + k;
            while ((int)(*(volatile unsigned*)&g_gen - target) < 0) __nanosleep(64);
        }
        __threadfence();
    }
    __syncthreads();
}

// add one bf16 row (uint4 = 8 bf16) into a[8] (rows are pre-scaled by dinv_src)
__device__ __forceinline__ void add_row(float* a, uint4 u) {
    float2 f;
    f = unpack2(u.x); a[0] += f.x; a[1] += f.y;
    f = unpack2(u.y); a[2] += f.x; a[3] += f.y;
    f = unpack2(u.z); a[4] += f.x; a[5] += f.y;
    f = unpack2(u.w); a[6] += f.x; a[7] += f.y;
}

// ---------------- fused GCN layer: prescaled-row-sum gather + HMMA GEMM -----
__device__ void layer_phase(const uint4* __restrict__ inb,       // prescaled bf16 rows
                            const unsigned short* __restrict__ Wt,
                            const float* __restrict__ bias,
                            const unsigned* __restrict__ resid,  // plain bf16 rows or null
                            unsigned* __restrict__ out_plain,
                            unsigned* __restrict__ out_scaled,
                            bool relu, int layer,
                            unsigned short* A_s, unsigned short* Ws, int* s_tile) {
    const int tid  = threadIdx.x;
    const int lane = tid & 31;
    const int wid  = tid >> 5;
    const unsigned baseA = smem_u32(A_s);
    const unsigned baseW = smem_u32(Ws);

    // ---- stage FULL W (256x256 bf16) into smem once per layer ----
    for (int i = tid; i < 8192; i += NT) {
        int n = i >> 5, o = i & 31;
        uint4 v = *(const uint4*)&Wt[n * 256 + o * 8];
        *(uint4*)&Ws[n * WST2 + o * 8] = v;
    }
    __syncthreads();

    for (;;) {
        __syncthreads();
        if (tid == 0) *s_tile = atomicAdd(&g_tctr[layer], 1);
        __syncthreads();
        const int tile = *s_tile;
        if (tile >= NTILE) break;
        const int r0 = tile * 64;

        // ---- gather: warp wid produces rows wid*4 .. wid*4+3 (cols lane*8..+7)
        for (int i = 0; i < 4; i++) {
            int rr = wid * 4 + i;
            int r  = r0 + rr;
            float a[8] = {0.f, 0.f, 0.f, 0.f, 0.f, 0.f, 0.f, 0.f};
            if (r < NP) {
                int beg = g_rowstart[r];
                int end = g_rowstart[r + 1];
                for (int base = beg; base < end; base += 32) {
                    int m = min(32, end - base);
                    int sidx = 0;
                    if (lane < m) sidx = g_csr_src[base + lane] * 32;
                    int k = 0;
                    for (; k + 4 <= m; k += 4) {
                        int i0 = __shfl_sync(0xffffffffu, sidx, k);
                        int i1 = __shfl_sync(0xffffffffu, sidx, k + 1);
                        int i2 = __shfl_sync(0xffffffffu, sidx, k + 2);
                        int i3 = __shfl_sync(0xffffffffu, sidx, k + 3);
                        uint4 u0 = inb[i0 + lane];
                        uint4 u1 = inb[i1 + lane];
                        uint4 u2 = inb[i2 + lane];
                        uint4 u3 = inb[i3 + lane];
                        add_row(a, u0);
                        add_row(a, u1);
                        add_row(a, u2);
                        add_row(a, u3);
                    }
                    for (; k < m; k++) {
                        int i0 = __shfl_sync(0xffffffffu, sidx, k);
                        uint4 u0 = inb[i0 + lane];
                        add_row(a, u0);
                    }
                }
                // self term: prescaled self row, then one final *dinv_r
                uint4 us = inb[r * 32 + lane];
                add_row(a, us);
                float di = g_dinv[r];
                #pragma unroll
                for (int j = 0; j < 8; j++) a[j] *= di;
            }
            uint4 pA;
            pA.x = pack2(a[0], a[1]); pA.y = pack2(a[2], a[3]);
            pA.z = pack2(a[4], a[5]); pA.w = pack2(a[6], a[7]);
            *(uint4*)&A_s[rr * AST2 + lane * 8] = pA;
        }
        __syncthreads();

        // ---- GEMM: H[64,256] = A_s(bf16) @ W(bf16) via mma.sync, W resident
        const int mg = wid & 3;
        const int ng = wid >> 2;
        const int g  = lane >> 3;
        float c[8][4];
        #pragma unroll
        for (int f = 0; f < 8; f++)
            #pragma unroll
            for (int q = 0; q < 4; q++) c[f][q] = 0.f;

        const int arow  = mg * 16 + (lane & 7) + (g & 1) * 8;
        const int akofs = (g >> 1) * 8;
        const unsigned aaddr0 = baseA + (unsigned)(arow * AST2 + akofs) * 2u;
        const int brow_base = ng * 64 + (lane & 7) + (g & 2) * 4;
        const int bkofs = (g & 1) * 8;

        #pragma unroll
        for (int kk = 0; kk < 256; kk += 16) {
            unsigned a0, a1, a2, a3;
            ldsm_x4(a0, a1, a2, a3, aaddr0 + (unsigned)kk * 2u);
            #pragma unroll
            for (int s = 0; s < 4; s++) {
                unsigned baddr = baseW +
                    (unsigned)((brow_base + s * 16) * WST2 + kk + bkofs) * 2u;
                unsigned b0, b1, b2, b3;
                ldsm_x4(b0, b1, b2, b3, baddr);
                mma_bf16(c[2 * s],     a0, a1, a2, a3, b0, b1);
                mma_bf16(c[2 * s + 1], a0, a1, a2, a3, b2, b3);
            }
        }

        // ---- epilogue: bias (+residual bf16) (+relu) -> plain / scaled bf16
        const int gr   = lane >> 2;
        const int colq = (lane & 3) * 2;
        #pragma unroll
        for (int f = 0; f < 8; f++) {
            int col = ng * 64 + f * 8 + colq;
            float2 bi = *(const float2*)&bias[col];
            #pragma unroll
            for (int half = 0; half < 2; half++) {
                int r = r0 + mg * 16 + gr + half * 8;
                if (r < NP) {
                    float vx = c[f][2 * half]     + bi.x;
                    float vy = c[f][2 * half + 1] + bi.y;
                    if (resid) {
                        float2 rr2 = unpack2(resid[r * 128 + (col >> 1)]);
                        vx += rr2.x; vy += rr2.y;
                    }
                    if (relu) { vx = fmaxf(vx, 0.f); vy = fmaxf(vy, 0.f); }
                    out_plain[r * 128 + (col >> 1)] = pack2(vx, vy);
                    if (out_scaled) {
                        float di = g_dinv[r];
                        out_scaled[r * 128 + (col >> 1)] = pack2(vx * di, vy * di);
                    }
                }
            }
        }
    }
}

// ---------------- the single mega-kernel ------------------------------------
__global__ __launch_bounds__(NT, 1) void mega_kernel(
    const float* __restrict__ x, const int* __restrict__ ddb,
    const int* __restrict__ src, const int* __restrict__ dst,
    const int* __restrict__ nodes, const int* __restrict__ avgix,
    const float* __restrict__ W1, const float* __restrict__ b1,
    const float* __restrict__ W2, const float* __restrict__ b2,
    float* __restrict__ out)
{
    extern __shared__ char smem_raw[];
    unsigned short* A_s = (unsigned short*)smem_raw;              // 33792B
    unsigned short* Ws  = (unsigned short*)(smem_raw + 33792);    // 135168B
    __shared__ unsigned s_gen0;
    __shared__ int s_tile;

    const int tid  = threadIdx.x;
    const int lane = tid & 31;
    const int wid  = tid >> 5;
    const int gtid = blockIdx.x * NT + tid;
    const int gs   = NB * NT;

    if (tid == 0) s_gen0 = *(volatile unsigned*)&g_gen;
    __syncthreads();
    const unsigned gen0 = s_gen0;

    // ---- P0: histogram + coalesced W->bf16^T + drug bounds + counters ----
    for (int e = gtid; e < E_SG; e += gs)
        atomicAdd(&g_deg[dst[e]], 1);
    // smem-tiled transpose: 64 tiles of 32x32 per W; blocks 0..127 do one tile
    if (blockIdx.x < 128) {
        const float* Win = (blockIdx.x < 64) ? W1 : W2;
        unsigned short* Wout = (blockIdx.x < 64) ? g_w1t : g_w2t;
        int tt = blockIdx.x & 63;
        int ty = tt >> 3;           // k-block
        int tx = tt & 7;            // n-block
        float* st = (float*)smem_raw;   // 32 x 33
        for (int idx = tid; idx < 1024; idx += NT) {
            int row = idx >> 5, colc = idx & 31;
            st[row * 33 + colc] = Win[(ty * 32 + row) * 256 + tx * 32 + colc];
        }
        __syncthreads();
        for (int idx = tid; idx < 1024; idx += NT) {
            int row = idx >> 5, colc = idx & 31;     // row = n-within, colc = k-within
            Wout[(tx * 32 + row) * 256 + ty * 32 + colc] = b16(st[colc * 33 + row]);
        }
    }
    if (gtid < 2) g_tctr[gtid] = 0;
    if (gtid <= ND) {
        if (gtid == ND) g_drug_start[ND] = N_SG;
        else {
            int lo = 0, hi = N_SG;
            while (lo < hi) {
                int mid = (lo + hi) >> 1;
                if (avgix[mid] < gtid) lo = mid + 1; else hi = mid;
            }
            g_drug_start[gtid] = lo;
        }
    }
    gridbar(gen0, 1);

    // ---- P1a: per-block chunk sums ----
    int* si = (int*)smem_raw;
    {
        int n0  = blockIdx.x * CHUNK;
        int len = NP - n0; if (len > CHUNK) len = CHUNK; if (len < 0) len = 0;
        int v = (tid < len) ? g_deg[n0 + tid] : 0;
        if (tid < CHUNK) si[tid] = v;
        __syncthreads();
        if (tid == 0) {
            int s = 0;
            for (int i = 0; i < len; i++) s += si[i];
            g_part[blockIdx.x] = s;
        }
    }
    gridbar(gen0, 2);

    // ---- P1b: block 0 scans the 148 partials ----
    if (blockIdx.x == 0) {
        int pv = (tid < NB) ? g_part[tid] : 0;
        if (tid < NB) si[tid] = pv;
        __syncthreads();
        if (tid == 0) {
            int run = 0;
            for (int i = 0; i < NB; i++) { int t = si[i]; si[i] = run; run += t; }
        }
        __syncthreads();
        if (tid < NB) g_poff[tid] = si[tid];
    }
    gridbar(gen0, 3);

    // ---- P1c: per-chunk prefix -> rowstart/fill/dinv ----
    {
        int n0  = blockIdx.x * CHUNK;
        int len = NP - n0; if (len > CHUNK) len = CHUNK; if (len < 0) len = 0;
        int v = (tid < len) ? g_deg[n0 + tid] : 0;
        if (tid < CHUNK) si[tid] = v;
        __syncthreads();
        if (tid == 0) {
            int run = g_poff[blockIdx.x];
            for (int i = 0; i < len; i++) { int t = si[i]; si[i] = run; run += t; }
        }
        __syncthreads();
        if (tid < len) {
            int node = n0 + tid;
            int rs = si[tid];
            g_rowstart[node] = rs;
            g_fill[node]     = rs;
            g_dinv[node]     = rsqrtf((float)v + 1.0f);
        }
        if (blockIdx.x == 0 && tid == 0) g_rowstart[NP] = E_SG;
    }
    gridbar(gen0, 4);

    // ---- P2: CSR fill + prescaled x->bf16 + reset g_deg ----
    for (int e = gtid; e < E_SG; e += gs) {
        int d   = dst[e];
        int pos = atomicAdd(&g_fill[d], 1);
        g_csr_src[pos] = src[e];
    }
    {
        const float2* x2 = (const float2*)x;
        for (int i = gtid; i < NP * 128; i += gs) {
            int r = i >> 7;
            float di = g_dinv[r];
            float2 v = x2[i];
            g_xb[i] = pack2(v.x * di, v.y * di);
        }
    }
    for (int i = gtid; i < NP; i += gs) g_deg[i] = 0;
    gridbar(gen0, 5);

    // ---- P3: layer 1  h1 = relu(agg + b1) -> plain bf16 + prescaled bf16 ----
    layer_phase((const uint4*)g_xb, g_w1t, b1, nullptr,
                g_h1b, g_h1sb, true, 0, A_s, Ws, &s_tile);
    gridbar(gen0, 6);

    // ---- P4: layer 2  h2 = agg + b2 + h1 -> plain bf16 only ----
    layer_phase((const uint4*)g_h1sb, g_w2t, b2, g_h1b,
                g_h2b, nullptr, false, 1, A_s, Ws, &s_tile);
    gridbar(gen0, 7);

    // ---- P5: scatter-mean pooling from bf16 h2 ----
    {
        const uint4* h2b = (const uint4*)g_h2b;
        float* P = (float*)smem_raw;
        for (int d = blockIdx.x; d < ND; d += NB) {
            int beg = g_drug_start[d];
            int end = g_drug_start[d + 1];
            float a[8] = {0.f, 0.f, 0.f, 0.f, 0.f, 0.f, 0.f, 0.f};
            for (int base = beg + wid * 32; base < end; base += NT) {
                int m = min(32, end - base);
                int nidx = 0;
                if (lane < m) nidx = nodes[base + lane] * 32;
                int k = 0;
                for (; k + 2 <= m; k += 2) {
                    int i0 = __shfl_sync(0xffffffffu, nidx, k);
                    int i1 = __shfl_sync(0xffffffffu, nidx, k + 1);
                    uint4 u0 = h2b[i0 + lane];
                    uint4 u1 = h2b[i1 + lane];
                    add_row(a, u0);
                    add_row(a, u1);
                }
                if (k < m) {
                    int i0 = __shfl_sync(0xffffffffu, nidx, k);
                    uint4 u0 = h2b[i0 + lane];
                    add_row(a, u0);
                }
            }
            __syncthreads();
            *(float4*)&P[wid * 256 + lane * 8]     = make_float4(a[0], a[1], a[2], a[3]);
            *(float4*)&P[wid * 256 + lane * 8 + 4] = make_float4(a[4], a[5], a[6], a[7]);
            __syncthreads();
            if (tid < 256) {
                float s = 0.f;
                #pragma unroll
                for (int w = 0; w < NWARP; w++) s += P[w * 256 + tid];
                float inv = 1.0f / fmaxf((float)(end - beg), 1.0f);
                g_drug[d * 256 + tid] = s * inv;
            }
            __syncthreads();
        }
    }
    gridbar(gen0, 8);

    // ---- P6: prediction head ----
    {
        const float4* gd = (const float4*)g_drug;
        for (int p = blockIdx.x * NWARP + wid; p < B_DD; p += NB * NWARP) {
            int a = ddb[p];
            int b = ddb[B_DD + p];
            float4 va0 = gd[a * 64 + lane], va1 = gd[a * 64 + 32 + lane];
            float4 vb0 = gd[b * 64 + lane], vb1 = gd[b * 64 + 32 + lane];
            float s = va0.x * vb0.x + va0.y * vb0.y + va0.z * vb0.z + va0.w * vb0.w
                    + va1.x * vb1.x + va1.y * vb1.y + va1.z * vb1.z + va1.w * vb1.w;
            #pragma unroll
            for (int off = 16; off; off >>= 1)
                s += __shfl_down_sync(0xffffffffu, s, off);
            if (lane == 0) out[p] = s;
        }
    }
}

// ---------------- launch ----------------------------------------------------
extern "C" void kernel_launch(void* const* d_in, const int* in_sizes, int n_in,
                              void* d_out, int out_size) {
    const float* x     = (const float*)d_in[0];
    const int*   ddb   = (const int*)d_in[1];
    const int*   sg_ei = (const int*)d_in[4];
    const int*   nodes = (const int*)d_in[5];
    const int*   avgix = (const int*)d_in[6];
    const float* W1    = (const float*)d_in[7];
    const float* b1    = (const float*)d_in[8];
    const float* W2    = (const float*)d_in[9];
    const float* b2    = (const float*)d_in[10];
    float* out = (float*)d_out;

    const int smem_bytes = 33792 + 135168;   // 168960
    static bool attr_set = false;
    if (!attr_set) {
        cudaFuncSetAttribute(mega_kernel, cudaFuncAttributeMaxDynamicSharedMemorySize,
                             smem_bytes);
        attr_set = true;
    }

    mega_kernel<<<NB, NT, smem_bytes>>>(x, ddb, sg_ei, sg_ei + E_SG,
                                        nodes, avgix, W1, b1, W2, b2, out);
}